// round 5
// baseline (speedup 1.0000x reference)
#include <cuda_runtime.h>
#include <math.h>
#include <stdint.h>

#define BB 8
#define CH 64
#define HH 128
#define WW 128

typedef unsigned long long u64;

// ---------------- scratch (device globals; no allocation allowed) ----------
__device__ float g_x_nhwc[BB*HH*WW*CH];   // x transposed to NHWC
__device__ float g_xh_nhwc[BB*HH*WW*CH];  // horizontal-pass output, NHWC
__device__ float g_omh[BB*HH*WW*12];      // dy0,dx0,dy1,dx1,dy2,dx2,m0,m1,m2,pad
__device__ float g_omv[BB*HH*WW*12];
// Pre-packed weight images: [pass][k][c][64 floats], row = 32 u64 out-pairs,
// u64 pos = i2*16 + og*2 + t  holds pair (w[2jg], w[2jg+1]), jg = og*4+i2*2+t
__device__ __align__(16) float g_wB[2][12288];

// ---------------- f32x2 packed helpers (Blackwell FFMA2) -------------------
static __device__ __forceinline__ u64 pk2(float a, float b) {
    u64 r; asm("mov.b64 %0, {%1,%2};" : "=l"(r) : "f"(a), "f"(b)); return r;
}
static __device__ __forceinline__ void upk2(u64 v, float &a, float &b) {
    asm("mov.b64 {%0,%1}, %2;" : "=f"(a), "=f"(b) : "l"(v));
}
static __device__ __forceinline__ u64 ffma2(u64 a, u64 b, u64 c) {
    u64 d; asm("fma.rn.f32x2 %0, %1, %2, %3;" : "=l"(d) : "l"(a), "l"(b), "l"(c)); return d;
}
static __device__ __forceinline__ float f4c(const float4 &v, int i) {
    return i == 0 ? v.x : (i == 1 ? v.y : (i == 2 ? v.z : v.w));
}

// ---------------- K-1: weight repack (runs once, tiny) ---------------------
__global__ __launch_bounds__(256) void prep_weights(
    const float* __restrict__ wh, const float* __restrict__ wv)
{
    int i = blockIdx.x*256 + threadIdx.x;   // 2*12288
    if (i >= 24576) return;
    int pass = i / 12288;
    int r = i % 12288;
    int k = r / 4096;
    int rr = r % 4096;
    int c = rr / 64;
    int f = rr % 64;
    int pos = f >> 1, e = f & 1;
    int i2 = pos >> 4, og = (pos >> 1) & 7, t = pos & 1;
    int jg = og*4 + i2*2 + t;
    int o = 2*jg + e;
    const float* w = pass ? wv : wh;
    g_wB[pass][r] = w[o*192 + c*3 + k];
}

// ---------------- K0: NCHW -> NHWC transpose -------------------------------
__global__ __launch_bounds__(256) void transpose_kernel(const float* __restrict__ in) {
    __shared__ float tile[CH][33];
    int n = blockIdx.z, y = blockIdx.y, x0 = blockIdx.x * 32;
    int tx = threadIdx.x, ty = threadIdx.y;
    #pragma unroll
    for (int c = ty; c < CH; c += 8)
        tile[c][tx] = in[(((size_t)n*CH + c)*HH + y)*WW + x0 + tx];
    __syncthreads();
    int t = ty*32 + tx;
    #pragma unroll
    for (int i = 0; i < 8; i++) {
        int idx = t + i*256;
        int px = idx >> 6, c = idx & 63;
        g_x_nhwc[(((size_t)n*HH + y)*WW + x0 + px)*CH + c] = tile[c][px];
    }
}

// ---------------- K1: offsets + masks for both passes (FFMA2) --------------
__global__ __launch_bounds__(256) void offmask_kernel(
    const float* __restrict__ woh, const float* __restrict__ boh,
    const float* __restrict__ wmh, const float* __restrict__ bmh,
    const float* __restrict__ wov, const float* __restrict__ bov,
    const float* __restrict__ wmv, const float* __restrict__ bmv)
{
    __shared__ float ws[64*6*12];
    int tid = threadIdx.x;
    for (int i = tid; i < 64*6*12; i += 256) {
        int o = i % 12, j = (i/12) % 6, c = i/72;
        float v = 0.f;
        if (o < 6)      v = (j < 3) ? woh[o*192 + c*3 + j] : wov[o*192 + c*3 + (j-3)];
        else if (o < 9) v = (j < 3) ? wmh[(o-6)*192 + c*3 + j] : wmv[(o-6)*192 + c*3 + (j-3)];
        ws[i] = v;
    }
    __syncthreads();

    int row = blockIdx.x*2 + (tid >> 7);
    int x   = tid & 127;
    size_t p = (size_t)row*WW + x;
    int y = row & 127;

    u64 aH01 = 0, aH23 = 0, aH45 = 0, aH67 = 0;
    u64 aV01 = 0, aV23 = 0, aV45 = 0, aV67 = 0;
    float aH8 = 0.f, aV8 = 0.f;

    const float* pc = g_x_nhwc + p*CH;
    bool hl = x > 0, hr = x < WW-1, vu = y > 0, vd = y < HH-1;
    const float* pl = pc - CH;
    const float* pr = pc + CH;
    const float* pu = pc - (size_t)WW*CH;
    const float* pd = pc + (size_t)WW*CH;
    const float4 Z = make_float4(0.f,0.f,0.f,0.f);

    for (int c4 = 0; c4 < 16; c4++) {
        float4 fc = *(const float4*)(pc + c4*4);
        float4 fl = hl ? *(const float4*)(pl + c4*4) : Z;
        float4 fr = hr ? *(const float4*)(pr + c4*4) : Z;
        float4 fu = vu ? *(const float4*)(pu + c4*4) : Z;
        float4 fd = vd ? *(const float4*)(pd + c4*4) : Z;
        #pragma unroll
        for (int cc = 0; cc < 4; cc++) {
            int c = c4*4 + cc;
            float vh[3] = { f4c(fl,cc), f4c(fc,cc), f4c(fr,cc) };
            float vv[3] = { f4c(fu,cc), f4c(fc,cc), f4c(fd,cc) };
            #pragma unroll
            for (int j = 0; j < 3; j++) {
                const float* wb = &ws[(c*6 + j)*12];
                ulonglong2 W0 = *(const ulonglong2*)(wb);
                ulonglong2 W1 = *(const ulonglong2*)(wb + 4);
                float w8 = wb[8];
                float v = vh[j];
                u64 vs = pk2(v, v);
                aH01 = ffma2(vs, W0.x, aH01);
                aH23 = ffma2(vs, W0.y, aH23);
                aH45 = ffma2(vs, W1.x, aH45);
                aH67 = ffma2(vs, W1.y, aH67);
                aH8  = fmaf(v, w8, aH8);

                const float* ub = &ws[(c*6 + j + 3)*12];
                ulonglong2 U0 = *(const ulonglong2*)(ub);
                ulonglong2 U1 = *(const ulonglong2*)(ub + 4);
                float u8 = ub[8];
                float u = vv[j];
                u64 us = pk2(u, u);
                aV01 = ffma2(us, U0.x, aV01);
                aV23 = ffma2(us, U0.y, aV23);
                aV45 = ffma2(us, U1.x, aV45);
                aV67 = ffma2(us, U1.y, aV67);
                aV8  = fmaf(u, u8, aV8);
            }
        }
    }

    float accH[9], accV[9];
    upk2(aH01, accH[0], accH[1]); upk2(aH23, accH[2], accH[3]);
    upk2(aH45, accH[4], accH[5]); upk2(aH67, accH[6], accH[7]); accH[8] = aH8;
    upk2(aV01, accV[0], accV[1]); upk2(aV23, accV[2], accV[3]);
    upk2(aV45, accV[4], accV[5]); upk2(aV67, accV[6], accV[7]); accV[8] = aV8;

    float mh0 = 1.f/(1.f + expf(-(accH[6] + __ldg(bmh+0))));
    float mh1 = 1.f/(1.f + expf(-(accH[7] + __ldg(bmh+1))));
    float mh2 = 1.f/(1.f + expf(-(accH[8] + __ldg(bmh+2))));
    float mv0 = 1.f/(1.f + expf(-(accV[6] + __ldg(bmv+0))));
    float mv1 = 1.f/(1.f + expf(-(accV[7] + __ldg(bmv+1))));
    float mv2 = 1.f/(1.f + expf(-(accV[8] + __ldg(bmv+2))));

    float* oh = g_omh + p*12;
    *(float4*)(oh + 0) = make_float4(accH[0]+__ldg(boh+0), accH[1]+__ldg(boh+1),
                                     accH[2]+__ldg(boh+2), accH[3]+__ldg(boh+3));
    *(float4*)(oh + 4) = make_float4(accH[4]+__ldg(boh+4), accH[5]+__ldg(boh+5), mh0, mh1);
    oh[8] = mh2;
    float* ov = g_omv + p*12;
    *(float4*)(ov + 0) = make_float4(accV[0]+__ldg(bov+0), accV[1]+__ldg(bov+1),
                                     accV[2]+__ldg(bov+2), accV[3]+__ldg(bov+3));
    *(float4*)(ov + 4) = make_float4(accV[4]+__ldg(bov+4), accV[5]+__ldg(bov+5), mv0, mv1);
    ov[8] = mv2;
}

// ---------------- K2/K3: deformable axial pass (8x8 register tile) ---------
// Block = 256 threads = 2 image rows = 256 px x 64 outs.
// Thread tile: 8 px (pgr = tid>>3) x 8 outs (og = tid&7).
// smem floats: Bs 12288 | As 64*260=16640 | cww 3072 | cbase 3072  => 140288 B
#define APITCH 260
#define SMF_B   0
#define SMF_A   12288
#define SMF_CW  (12288 + 64*APITCH)
#define SMF_CB  (SMF_CW + 3072)
#define SMF_TOT (SMF_CB + 3072)

template<int VERT, int OUT_NCHW>
__global__ __launch_bounds__(256, 1) void pass_kernel(
    const float* __restrict__ src,   // NHWC input
    const float* __restrict__ om,    // stride-12 offset/mask records
    const float* __restrict__ wB,    // packed weights [3][64][64]
    const float* __restrict__ bias,
    float* __restrict__ dst)
{
    extern __shared__ float smem[];
    float* Bs   = smem + SMF_B;
    float* As   = smem + SMF_A;
    float* cww  = smem + SMF_CW;
    int*  cbase = (int*)(smem + SMF_CB);

    int tid = threadIdx.x, wid = tid >> 5, lane = tid & 31;
    int blk = blockIdx.x;               // 0..511, covers rows 2blk, 2blk+1
    int n = blk >> 6;
    int y0 = (blk*2) & 127;

    // stage packed weights (coalesced)
    {
        const float4* s4 = (const float4*)wB;
        float4* d4 = (float4*)Bs;
        #pragma unroll
        for (int i = 0; i < 12; i++)
            d4[tid + i*256] = s4[tid + i*256];
    }

    // per-pixel, per-tap corner weights + clamped base offsets
    for (int t = tid; t < 768; t += 256) {
        int k = t >> 8, p = t & 255;
        int yy = y0 + (p >> 7), xp = p & 127;
        const float* omb = om + ((size_t)blk*256 + p)*12;
        float dyk = omb[2*k], dxk = omb[2*k + 1], mkk = omb[6 + k];
        float py = (float)yy + dyk + (VERT ? (float)(k-1) : 0.f);
        float pxf = (float)xp + dxk + (VERT ? 0.f : (float)(k-1));
        float y0f = floorf(py), x0f = floorf(pxf);
        float wy = py - y0f, wx = pxf - x0f;
        int iy0 = (int)y0f, ix0 = (int)x0f;
        int iy1 = iy0 + 1,  ix1 = ix0 + 1;
        float vy0 = (iy0 >= 0 && iy0 < HH) ? 1.f : 0.f;
        float vy1 = (iy1 >= 0 && iy1 < HH) ? 1.f : 0.f;
        float vx0 = (ix0 >= 0 && ix0 < WW) ? 1.f : 0.f;
        float vx1 = (ix1 >= 0 && ix1 < WW) ? 1.f : 0.f;
        float* cw = &cww[(k*256 + p)*4];
        cw[0] = (1.f-wy)*(1.f-wx)*vy0*vx0*mkk;
        cw[1] = (1.f-wy)*wx      *vy0*vx1*mkk;
        cw[2] = wy*(1.f-wx)      *vy1*vx0*mkk;
        cw[3] = wy*wx            *vy1*vx1*mkk;
        int cy0 = min(max(iy0,0),HH-1), cy1 = min(max(iy1,0),HH-1);
        int cx0 = min(max(ix0,0),WW-1), cx1 = min(max(ix1,0),WW-1);
        int* cb = &cbase[(k*256 + p)*4];
        cb[0] = ((n*HH + cy0)*WW + cx0)*CH;
        cb[1] = ((n*HH + cy0)*WW + cx1)*CH;
        cb[2] = ((n*HH + cy1)*WW + cx0)*CH;
        cb[3] = ((n*HH + cy1)*WW + cx1)*CH;
    }
    __syncthreads();

    int p8 = lane >> 3, c8l = lane & 7;     // gather lane roles
    int og = tid & 7, pgr = tid >> 3;       // phase-B tile roles

    u64 acc[8][4];
    #pragma unroll
    for (int i = 0; i < 8; i++)
        #pragma unroll
        for (int j = 0; j < 4; j++) acc[i][j] = 0ull;

    for (int k = 0; k < 3; k++) {
        if (k) __syncthreads();

        // -------- gather: bilinear samples -> As[c][px] (channel-major) ----
        #pragma unroll
        for (int i = 0; i < 8; i++) {
            int px = i*32 + wid*4 + p8;
            const float* cw = &cww[(k*256 + px)*4];
            const int*   cb = &cbase[(k*256 + px)*4];
            float w00 = cw[0], w01 = cw[1], w10 = cw[2], w11 = cw[3];
            int b00 = cb[0], b01 = cb[1], b10 = cb[2], b11 = cb[3];
            #pragma unroll
            for (int h = 0; h < 2; h++) {
                int c4g = h*8 + c8l;            // 4-channel group 0..15
                int co = c4g*4;
                float4 v00 = *(const float4*)(src + b00 + co);
                float4 v01 = *(const float4*)(src + b01 + co);
                float4 v10 = *(const float4*)(src + b10 + co);
                float4 v11 = *(const float4*)(src + b11 + co);
                float* ar = As + co*APITCH + px;
                ar[0*APITCH] = fmaf(w00,v00.x, fmaf(w01,v01.x, fmaf(w10,v10.x, w11*v11.x)));
                ar[1*APITCH] = fmaf(w00,v00.y, fmaf(w01,v01.y, fmaf(w10,v10.y, w11*v11.y)));
                ar[2*APITCH] = fmaf(w00,v00.z, fmaf(w01,v01.z, fmaf(w10,v10.z, w11*v11.z)));
                ar[3*APITCH] = fmaf(w00,v00.w, fmaf(w01,v01.w, fmaf(w10,v10.w, w11*v11.w)));
            }
        }
        __syncthreads();

        // -------- phase B: 64-channel GEMM accumulate ----------------------
        const float* bk = Bs + k*4096;
        #pragma unroll 4
        for (int c = 0; c < 64; c++) {
            const float* arow = As + c*APITCH + pgr*8;
            float4 a0 = *(const float4*)(arow);
            float4 a1 = *(const float4*)(arow + 4);
            const float* brow = bk + c*64;
            ulonglong2 bp0 = *(const ulonglong2*)(brow + og*4);        // outs 0-3
            ulonglong2 bp1 = *(const ulonglong2*)(brow + 32 + og*4);   // outs 4-7
            u64 W0 = bp0.x, W1 = bp0.y, W2 = bp1.x, W3 = bp1.y;
            #pragma unroll
            for (int i = 0; i < 8; i++) {
                float av = (i < 4) ? f4c(a0, i) : f4c(a1, i - 4);
                u64 ad = pk2(av, av);
                acc[i][0] = ffma2(ad, W0, acc[i][0]);
                acc[i][1] = ffma2(ad, W1, acc[i][1]);
                acc[i][2] = ffma2(ad, W2, acc[i][2]);
                acc[i][3] = ffma2(ad, W3, acc[i][3]);
            }
        }
    }

    // -------- epilogue: add bias, store -----------------------------------
    float bv[8];
    #pragma unroll
    for (int m = 0; m < 8; m++) bv[m] = __ldg(bias + og*8 + m);

    if (OUT_NCHW) {
        int px0 = pgr*8;
        int yy = y0 + (px0 >> 7), x0 = px0 & 127;
        #pragma unroll
        for (int m = 0; m < 8; m++) {
            int j = m >> 1, t = m & 1;
            float v[8];
            #pragma unroll
            for (int i = 0; i < 8; i++) {
                float lo, hi; upk2(acc[i][j], lo, hi);
                v[i] = (t ? hi : lo) + bv[m];
            }
            float* db = dst + (((size_t)(n*CH + og*8 + m))*HH + yy)*WW + x0;
            *(float4*)(db)     = make_float4(v[0], v[1], v[2], v[3]);
            *(float4*)(db + 4) = make_float4(v[4], v[5], v[6], v[7]);
        }
    } else {
        #pragma unroll
        for (int i = 0; i < 8; i++) {
            int px = pgr*8 + i;
            float s[8];
            #pragma unroll
            for (int j = 0; j < 4; j++) {
                float lo, hi; upk2(acc[i][j], lo, hi);
                s[2*j]   = lo + bv[2*j];
                s[2*j+1] = hi + bv[2*j+1];
            }
            float* db = dst + ((size_t)blk*256 + px)*CH + og*8;
            *(float4*)(db)     = make_float4(s[0], s[1], s[2], s[3]);
            *(float4*)(db + 4) = make_float4(s[4], s[5], s[6], s[7]);
        }
    }
}

// ---------------- launch ---------------------------------------------------
extern "C" void kernel_launch(void* const* d_in, const int* in_sizes, int n_in,
                              void* d_out, int out_size) {
    const float* x        = (const float*)d_in[0];
    const float* w_off_h  = (const float*)d_in[1];
    const float* b_off_h  = (const float*)d_in[2];
    const float* w_mask_h = (const float*)d_in[3];
    const float* b_mask_h = (const float*)d_in[4];
    const float* w_off_v  = (const float*)d_in[5];
    const float* b_off_v  = (const float*)d_in[6];
    const float* w_mask_v = (const float*)d_in[7];
    const float* b_mask_v = (const float*)d_in[8];
    const float* w_h      = (const float*)d_in[9];
    const float* b_h      = (const float*)d_in[10];
    const float* w_v      = (const float*)d_in[11];
    const float* b_v      = (const float*)d_in[12];
    float* out = (float*)d_out;

    void *xn_p, *xh_p, *omh_p, *omv_p, *wB_p;
    cudaGetSymbolAddress(&xn_p,  g_x_nhwc);
    cudaGetSymbolAddress(&xh_p,  g_xh_nhwc);
    cudaGetSymbolAddress(&omh_p, g_omh);
    cudaGetSymbolAddress(&omv_p, g_omv);
    cudaGetSymbolAddress(&wB_p,  g_wB);
    const float* xn  = (const float*)xn_p;
    float*       xh  = (float*)xh_p;
    const float* omh = (const float*)omh_p;
    const float* omv = (const float*)omv_p;
    const float* wBh = (const float*)wB_p;
    const float* wBv = wBh + 12288;

    int smem_bytes = SMF_TOT * 4;   // 140288 B
    cudaFuncSetAttribute(pass_kernel<0,0>,
                         cudaFuncAttributeMaxDynamicSharedMemorySize, smem_bytes);
    cudaFuncSetAttribute(pass_kernel<1,1>,
                         cudaFuncAttributeMaxDynamicSharedMemorySize, smem_bytes);

    prep_weights<<<96, 256>>>(w_h, w_v);

    transpose_kernel<<<dim3(WW/32, HH, BB), dim3(32, 8)>>>(x);

    offmask_kernel<<<BB*HH/2, 256>>>(w_off_h, b_off_h, w_mask_h, b_mask_h,
                                     w_off_v, b_off_v, w_mask_v, b_mask_v);

    pass_kernel<0, 0><<<BB*HH/2, 256, smem_bytes>>>(xn, omh, wBh, b_h, xh);
    pass_kernel<1, 1><<<BB*HH/2, 256, smem_bytes>>>((const float*)xh, omv, wBv, b_v, out);
}

// round 6
// speedup vs baseline: 1.2428x; 1.2428x over previous
#include <cuda_runtime.h>
#include <math.h>
#include <stdint.h>

#define BB 8
#define CH 64
#define HH 128
#define WW 128

typedef unsigned long long u64;

// ---------------- scratch (device globals; no allocation allowed) ----------
__device__ float g_x_nhwc[BB*HH*WW*CH];   // x transposed to NHWC
__device__ float g_xh_nhwc[BB*HH*WW*CH];  // horizontal-pass output, NHWC
__device__ float g_omh[BB*HH*WW*12];      // dy0,dx0,dy1,dx1,dy2,dx2,m0,m1,m2,pad
__device__ float g_omv[BB*HH*WW*12];
// Packed weight images: [pass][k][c][64 floats]; row = 32 u64 out-pairs:
// u64 pos = i2*16 + og*2 + t holds (w[2jg], w[2jg+1]), jg = og*4 + i2*2 + t
__device__ __align__(16) float g_wB[2][12288];

// ---------------- f32x2 packed helpers (Blackwell FFMA2) -------------------
static __device__ __forceinline__ u64 pk2(float a, float b) {
    u64 r; asm("mov.b64 %0, {%1,%2};" : "=l"(r) : "f"(a), "f"(b)); return r;
}
static __device__ __forceinline__ void upk2(u64 v, float &a, float &b) {
    asm("mov.b64 {%0,%1}, %2;" : "=f"(a), "=f"(b) : "l"(v));
}
static __device__ __forceinline__ u64 ffma2(u64 a, u64 b, u64 c) {
    u64 d; asm("fma.rn.f32x2 %0, %1, %2, %3;" : "=l"(d) : "l"(a), "l"(b), "l"(c)); return d;
}
static __device__ __forceinline__ float f4c(const float4 &v, int i) {
    return i == 0 ? v.x : (i == 1 ? v.y : (i == 2 ? v.z : v.w));
}

// ---------------- K-1: weight repack (runs once, tiny) ---------------------
__global__ __launch_bounds__(256) void prep_weights(
    const float* __restrict__ wh, const float* __restrict__ wv)
{
    int i = blockIdx.x*256 + threadIdx.x;
    if (i >= 24576) return;
    int pass = i / 12288;
    int r = i % 12288;
    int k = r / 4096;
    int rr = r % 4096;
    int c = rr / 64;
    int f = rr % 64;
    int pos = f >> 1, e = f & 1;
    int i2 = pos >> 4, og = (pos >> 1) & 7, t = pos & 1;
    int jg = og*4 + i2*2 + t;
    int o = 2*jg + e;
    const float* w = pass ? wv : wh;
    g_wB[pass][r] = w[o*192 + c*3 + k];
}

// ---------------- K0: NCHW -> NHWC transpose -------------------------------
__global__ __launch_bounds__(256) void transpose_kernel(const float* __restrict__ in) {
    __shared__ float tile[CH][33];
    int n = blockIdx.z, y = blockIdx.y, x0 = blockIdx.x * 32;
    int tx = threadIdx.x, ty = threadIdx.y;
    #pragma unroll
    for (int c = ty; c < CH; c += 8)
        tile[c][tx] = in[(((size_t)n*CH + c)*HH + y)*WW + x0 + tx];
    __syncthreads();
    int t = ty*32 + tx;
    #pragma unroll
    for (int i = 0; i < 8; i++) {
        int idx = t + i*256;
        int px = idx >> 6, c = idx & 63;
        g_x_nhwc[(((size_t)n*HH + y)*WW + x0 + px)*CH + c] = tile[c][px];
    }
}

// ---------------- K1: offsets + masks, 2 pixels (adjacent rows) / thread ---
__global__ __launch_bounds__(256, 2) void offmask_kernel(
    const float* __restrict__ woh, const float* __restrict__ boh,
    const float* __restrict__ wmh, const float* __restrict__ bmh,
    const float* __restrict__ wov, const float* __restrict__ bov,
    const float* __restrict__ wmv, const float* __restrict__ bmv)
{
    __shared__ float ws[64*6*12];
    int tid = threadIdx.x;
    for (int i = tid; i < 64*6*12; i += 256) {
        int o = i % 12, j = (i/12) % 6, c = i/72;
        float v = 0.f;
        if (o < 6)      v = (j < 3) ? woh[o*192 + c*3 + j] : wov[o*192 + c*3 + (j-3)];
        else if (o < 9) v = (j < 3) ? wmh[(o-6)*192 + c*3 + j] : wmv[(o-6)*192 + c*3 + (j-3)];
        ws[i] = v;
    }
    __syncthreads();

    int x = tid & 127;
    int pairidx = blockIdx.x*2 + (tid >> 7);   // 0..511
    int row0 = pairidx*2;                      // even row, row1 = row0+1 (same image)
    int y = row0 & 127;                        // even, 0..126
    size_t p0 = (size_t)row0*WW + x;
    size_t p1 = p0 + WW;

    u64 H0a=0,H0b=0,H0c=0,H0d=0, V0a=0,V0b=0,V0c=0,V0d=0;
    u64 H1a=0,H1b=0,H1c=0,H1d=0, V1a=0,V1b=0,V1c=0,V1d=0;
    float H0e=0.f, V0e=0.f, H1e=0.f, V1e=0.f;

    const float* pc0 = g_x_nhwc + p0*CH;   // row y
    const float* pc1 = g_x_nhwc + p1*CH;   // row y+1
    bool hl = x > 0, hr = x < WW-1;
    bool vu = y > 0, vd = (y + 2) < HH;
    const float* pl0 = pc0 - CH;
    const float* pr0 = pc0 + CH;
    const float* pl1 = pc1 - CH;
    const float* pr1 = pc1 + CH;
    const float* pu  = pc0 - (size_t)WW*CH;   // row y-1
    const float* pd  = pc1 + (size_t)WW*CH;   // row y+2
    const float4 Z = make_float4(0.f,0.f,0.f,0.f);

    for (int c4 = 0; c4 < 16; c4++) {
        float4 fc0 = *(const float4*)(pc0 + c4*4);
        float4 fc1 = *(const float4*)(pc1 + c4*4);
        float4 fl0 = hl ? *(const float4*)(pl0 + c4*4) : Z;
        float4 fr0 = hr ? *(const float4*)(pr0 + c4*4) : Z;
        float4 fl1 = hl ? *(const float4*)(pl1 + c4*4) : Z;
        float4 fr1 = hr ? *(const float4*)(pr1 + c4*4) : Z;
        float4 fu  = vu ? *(const float4*)(pu  + c4*4) : Z;
        float4 fd  = vd ? *(const float4*)(pd  + c4*4) : Z;
        #pragma unroll
        for (int cc = 0; cc < 4; cc++) {
            int c = c4*4 + cc;
            float h0[3] = { f4c(fl0,cc), f4c(fc0,cc), f4c(fr0,cc) };
            float h1[3] = { f4c(fl1,cc), f4c(fc1,cc), f4c(fr1,cc) };
            float v0[3] = { f4c(fu,cc),  f4c(fc0,cc), f4c(fc1,cc) };
            float v1[3] = { f4c(fc0,cc), f4c(fc1,cc), f4c(fd,cc)  };
            #pragma unroll
            for (int j = 0; j < 3; j++) {
                const float* wb = &ws[(c*6 + j)*12];
                ulonglong2 W0 = *(const ulonglong2*)(wb);
                ulonglong2 W1 = *(const ulonglong2*)(wb + 4);
                float w8 = wb[8];
                u64 s0 = pk2(h0[j], h0[j]);
                H0a = ffma2(s0, W0.x, H0a); H0b = ffma2(s0, W0.y, H0b);
                H0c = ffma2(s0, W1.x, H0c); H0d = ffma2(s0, W1.y, H0d);
                H0e = fmaf(h0[j], w8, H0e);
                u64 s1 = pk2(h1[j], h1[j]);
                H1a = ffma2(s1, W0.x, H1a); H1b = ffma2(s1, W0.y, H1b);
                H1c = ffma2(s1, W1.x, H1c); H1d = ffma2(s1, W1.y, H1d);
                H1e = fmaf(h1[j], w8, H1e);

                const float* ub = &ws[(c*6 + j + 3)*12];
                ulonglong2 U0 = *(const ulonglong2*)(ub);
                ulonglong2 U1 = *(const ulonglong2*)(ub + 4);
                float u8 = ub[8];
                u64 t0 = pk2(v0[j], v0[j]);
                V0a = ffma2(t0, U0.x, V0a); V0b = ffma2(t0, U0.y, V0b);
                V0c = ffma2(t0, U1.x, V0c); V0d = ffma2(t0, U1.y, V0d);
                V0e = fmaf(v0[j], u8, V0e);
                u64 t1 = pk2(v1[j], v1[j]);
                V1a = ffma2(t1, U0.x, V1a); V1b = ffma2(t1, U0.y, V1b);
                V1c = ffma2(t1, U1.x, V1c); V1d = ffma2(t1, U1.y, V1d);
                V1e = fmaf(v1[j], u8, V1e);
            }
        }
    }

    float b0 = __ldg(boh+0), b1 = __ldg(boh+1), b2 = __ldg(boh+2);
    float b3 = __ldg(boh+3), b4 = __ldg(boh+4), b5 = __ldg(boh+5);
    float c0 = __ldg(bov+0), c1 = __ldg(bov+1), c2 = __ldg(bov+2);
    float c3 = __ldg(bov+3), c4b = __ldg(bov+4), c5 = __ldg(bov+5);
    float mb0 = __ldg(bmh+0), mb1 = __ldg(bmh+1), mb2 = __ldg(bmh+2);
    float nb0 = __ldg(bmv+0), nb1 = __ldg(bmv+1), nb2 = __ldg(bmv+2);

    #pragma unroll
    for (int r = 0; r < 2; r++) {
        float A[9], V[9];
        if (r == 0) {
            upk2(H0a,A[0],A[1]); upk2(H0b,A[2],A[3]); upk2(H0c,A[4],A[5]);
            upk2(H0d,A[6],A[7]); A[8]=H0e;
            upk2(V0a,V[0],V[1]); upk2(V0b,V[2],V[3]); upk2(V0c,V[4],V[5]);
            upk2(V0d,V[6],V[7]); V[8]=V0e;
        } else {
            upk2(H1a,A[0],A[1]); upk2(H1b,A[2],A[3]); upk2(H1c,A[4],A[5]);
            upk2(H1d,A[6],A[7]); A[8]=H1e;
            upk2(V1a,V[0],V[1]); upk2(V1b,V[2],V[3]); upk2(V1c,V[4],V[5]);
            upk2(V1d,V[6],V[7]); V[8]=V1e;
        }
        size_t p = r ? p1 : p0;
        float mh0 = 1.f/(1.f + expf(-(A[6] + mb0)));
        float mh1 = 1.f/(1.f + expf(-(A[7] + mb1)));
        float mh2 = 1.f/(1.f + expf(-(A[8] + mb2)));
        float mv0 = 1.f/(1.f + expf(-(V[6] + nb0)));
        float mv1 = 1.f/(1.f + expf(-(V[7] + nb1)));
        float mv2 = 1.f/(1.f + expf(-(V[8] + nb2)));
        float* oh = g_omh + p*12;
        *(float4*)(oh+0) = make_float4(A[0]+b0, A[1]+b1, A[2]+b2, A[3]+b3);
        *(float4*)(oh+4) = make_float4(A[4]+b4, A[5]+b5, mh0, mh1);
        oh[8] = mh2;
        float* ov = g_omv + p*12;
        *(float4*)(ov+0) = make_float4(V[0]+c0, V[1]+c1, V[2]+c2, V[3]+c3);
        *(float4*)(ov+4) = make_float4(V[4]+c4b, V[5]+c5, mv0, mv1);
        ov[8] = mv2;
    }
}

// ---------------- K2/K3: deformable axial pass ------------------------------
// Block = 256 thr, 1 row = 128 px x 64 outs; thread tile 4 px x 8 outs.
// smem floats: Bs 12288 | As 64*128 (XOR-swizzled) | cww 1536 | cbase 1536
#define SMF_B   0
#define SMF_A   12288
#define SMF_CW  (12288 + 8192)
#define SMF_CB  (SMF_CW + 1536)
#define SMF_TOT (SMF_CB + 1536)     // 23552 floats = 94208 B

template<int VERT, int OUT_NCHW>
__global__ __launch_bounds__(256, 2) void pass_kernel(
    const float* __restrict__ src,   // NHWC input
    const float* __restrict__ om,    // stride-12 offset/mask records
    const float* __restrict__ wB,    // packed weights [3][64][64]
    const float* __restrict__ bias,
    float* __restrict__ dst)
{
    extern __shared__ float smem[];
    float* Bs   = smem + SMF_B;
    float* As   = smem + SMF_A;
    float* cww  = smem + SMF_CW;
    int*  cbase = (int*)(smem + SMF_CB);

    int tid = threadIdx.x, wid = tid >> 5, lane = tid & 31;
    int row = blockIdx.x;            // n*H + y
    int n = row >> 7, y = row & 127;

    // stage packed weights (coalesced)
    {
        const float4* s4 = (const float4*)wB;
        float4* d4 = (float4*)Bs;
        #pragma unroll
        for (int i = 0; i < 12; i++)
            d4[tid + i*256] = s4[tid + i*256];
    }

    // per-pixel, per-tap corner weights + clamped base offsets
    for (int t = tid; t < 384; t += 256) {
        int k = t >> 7, xp = t & 127;
        const float* omb = om + ((size_t)row*WW + xp)*12;
        float dyk = omb[2*k], dxk = omb[2*k + 1], mkk = omb[6 + k];
        float py = (float)y + dyk + (VERT ? (float)(k-1) : 0.f);
        float pxf = (float)xp + dxk + (VERT ? 0.f : (float)(k-1));
        float y0f = floorf(py), x0f = floorf(pxf);
        float wy = py - y0f, wx = pxf - x0f;
        int iy0 = (int)y0f, ix0 = (int)x0f;
        int iy1 = iy0 + 1,  ix1 = ix0 + 1;
        float vy0 = (iy0 >= 0 && iy0 < HH) ? 1.f : 0.f;
        float vy1 = (iy1 >= 0 && iy1 < HH) ? 1.f : 0.f;
        float vx0 = (ix0 >= 0 && ix0 < WW) ? 1.f : 0.f;
        float vx1 = (ix1 >= 0 && ix1 < WW) ? 1.f : 0.f;
        float* cw = &cww[(k*128 + xp)*4];
        cw[0] = (1.f-wy)*(1.f-wx)*vy0*vx0*mkk;
        cw[1] = (1.f-wy)*wx      *vy0*vx1*mkk;
        cw[2] = wy*(1.f-wx)      *vy1*vx0*mkk;
        cw[3] = wy*wx            *vy1*vx1*mkk;
        int cy0 = min(max(iy0,0),HH-1), cy1 = min(max(iy1,0),HH-1);
        int cx0 = min(max(ix0,0),WW-1), cx1 = min(max(ix1,0),WW-1);
        int* cb = &cbase[(k*128 + xp)*4];
        cb[0] = ((n*HH + cy0)*WW + cx0)*CH;
        cb[1] = ((n*HH + cy0)*WW + cx1)*CH;
        cb[2] = ((n*HH + cy1)*WW + cx0)*CH;
        cb[3] = ((n*HH + cy1)*WW + cx1)*CH;
    }
    __syncthreads();

    int p8 = lane >> 3, c8l = lane & 7;     // gather lane roles
    int og = tid & 7, pgr = tid >> 3;       // phase-B: outs og*8.., px pgr*4..

    u64 acc[4][4];
    #pragma unroll
    for (int i = 0; i < 4; i++)
        #pragma unroll
        for (int j = 0; j < 4; j++) acc[i][j] = 0ull;

    for (int k = 0; k < 3; k++) {
        if (k) __syncthreads();

        // -------- gather: bilinear samples -> As[c][px], XOR-swizzled ------
        #pragma unroll
        for (int i = 0; i < 4; i++) {
            int pxg = wid*4 + i;                 // pixel group (4 px)
            int px = pxg*4 + p8;
            const float* cw = &cww[(k*128 + px)*4];
            const int*   cb = &cbase[(k*128 + px)*4];
            float w00 = cw[0], w01 = cw[1], w10 = cw[2], w11 = cw[3];
            int b00 = cb[0], b01 = cb[1], b10 = cb[2], b11 = cb[3];
            #pragma unroll
            for (int h = 0; h < 2; h++) {
                int c4g = h*8 + c8l;             // channel group 0..15
                int co = c4g*4;
                float4 v00 = *(const float4*)(src + b00 + co);
                float4 v01 = *(const float4*)(src + b01 + co);
                float4 v10 = *(const float4*)(src + b10 + co);
                float4 v11 = *(const float4*)(src + b11 + co);
                // swizzle shift s = c4g & 7 (same for the 4 comps)
                int base = ((pxg ^ (c4g & 7)) << 2) + p8;
                float* ar = As + co*128 + base;
                ar[0*128] = fmaf(w00,v00.x, fmaf(w01,v01.x, fmaf(w10,v10.x, w11*v11.x)));
                ar[1*128] = fmaf(w00,v00.y, fmaf(w01,v01.y, fmaf(w10,v10.y, w11*v11.y)));
                ar[2*128] = fmaf(w00,v00.z, fmaf(w01,v01.z, fmaf(w10,v10.z, w11*v11.z)));
                ar[3*128] = fmaf(w00,v00.w, fmaf(w01,v01.w, fmaf(w10,v10.w, w11*v11.w)));
            }
        }
        __syncthreads();

        // -------- phase B: 64-channel GEMM accumulate ----------------------
        const float* bk = Bs + k*4096;
        #pragma unroll 8
        for (int c = 0; c < 64; c++) {
            int s = (c >> 2) & 7;
            float4 a = *(const float4*)(As + c*128 + ((pgr ^ s) << 2));
            const float* brow = bk + c*64;
            ulonglong2 bp0 = *(const ulonglong2*)(brow + og*4);       // outs 0-3
            ulonglong2 bp1 = *(const ulonglong2*)(brow + 32 + og*4);  // outs 4-7
            u64 W0 = bp0.x, W1 = bp0.y, W2 = bp1.x, W3 = bp1.y;
            #pragma unroll
            for (int i = 0; i < 4; i++) {
                float av = f4c(a, i);
                u64 ad = pk2(av, av);
                acc[i][0] = ffma2(ad, W0, acc[i][0]);
                acc[i][1] = ffma2(ad, W1, acc[i][1]);
                acc[i][2] = ffma2(ad, W2, acc[i][2]);
                acc[i][3] = ffma2(ad, W3, acc[i][3]);
            }
        }
    }

    // -------- epilogue: add bias, store -----------------------------------
    float bv[8];
    #pragma unroll
    for (int m = 0; m < 8; m++) bv[m] = __ldg(bias + og*8 + m);

    if (OUT_NCHW) {
        #pragma unroll
        for (int m = 0; m < 8; m++) {
            int j = m >> 1, t = m & 1;
            float v[4];
            #pragma unroll
            for (int i = 0; i < 4; i++) {
                float lo, hi; upk2(acc[i][j], lo, hi);
                v[i] = (t ? hi : lo) + bv[m];
            }
            float* db = dst + (((size_t)(n*CH + og*8 + m))*HH + y)*WW + pgr*4;
            *(float4*)db = make_float4(v[0], v[1], v[2], v[3]);
        }
    } else {
        #pragma unroll
        for (int i = 0; i < 4; i++) {
            int px = pgr*4 + i;
            float s[8];
            #pragma unroll
            for (int j = 0; j < 4; j++) {
                float lo, hi; upk2(acc[i][j], lo, hi);
                s[2*j]   = lo + bv[2*j];
                s[2*j+1] = hi + bv[2*j+1];
            }
            float* db = dst + ((size_t)row*WW + px)*CH + og*8;
            *(float4*)(db)     = make_float4(s[0], s[1], s[2], s[3]);
            *(float4*)(db + 4) = make_float4(s[4], s[5], s[6], s[7]);
        }
    }
}

// ---------------- launch ---------------------------------------------------
extern "C" void kernel_launch(void* const* d_in, const int* in_sizes, int n_in,
                              void* d_out, int out_size) {
    const float* x        = (const float*)d_in[0];
    const float* w_off_h  = (const float*)d_in[1];
    const float* b_off_h  = (const float*)d_in[2];
    const float* w_mask_h = (const float*)d_in[3];
    const float* b_mask_h = (const float*)d_in[4];
    const float* w_off_v  = (const float*)d_in[5];
    const float* b_off_v  = (const float*)d_in[6];
    const float* w_mask_v = (const float*)d_in[7];
    const float* b_mask_v = (const float*)d_in[8];
    const float* w_h      = (const float*)d_in[9];
    const float* b_h      = (const float*)d_in[10];
    const float* w_v      = (const float*)d_in[11];
    const float* b_v      = (const float*)d_in[12];
    float* out = (float*)d_out;

    void *xn_p, *xh_p, *omh_p, *omv_p, *wB_p;
    cudaGetSymbolAddress(&xn_p,  g_x_nhwc);
    cudaGetSymbolAddress(&xh_p,  g_xh_nhwc);
    cudaGetSymbolAddress(&omh_p, g_omh);
    cudaGetSymbolAddress(&omv_p, g_omv);
    cudaGetSymbolAddress(&wB_p,  g_wB);
    const float* xn  = (const float*)xn_p;
    float*       xh  = (float*)xh_p;
    const float* omh = (const float*)omh_p;
    const float* omv = (const float*)omv_p;
    const float* wBh = (const float*)wB_p;
    const float* wBv = wBh + 12288;

    int smem_bytes = SMF_TOT * 4;   // 94208 B
    cudaFuncSetAttribute(pass_kernel<0,0>,
                         cudaFuncAttributeMaxDynamicSharedMemorySize, smem_bytes);
    cudaFuncSetAttribute(pass_kernel<1,1>,
                         cudaFuncAttributeMaxDynamicSharedMemorySize, smem_bytes);

    prep_weights<<<96, 256>>>(w_h, w_v);

    transpose_kernel<<<dim3(WW/32, HH, BB), dim3(32, 8)>>>(x);

    offmask_kernel<<<BB*HH/4, 256>>>(w_off_h, b_off_h, w_mask_h, b_mask_h,
                                     w_off_v, b_off_v, w_mask_v, b_mask_v);

    pass_kernel<0, 0><<<BB*HH, 256, smem_bytes>>>(xn, omh, wBh, b_h, xh);
    pass_kernel<1, 1><<<BB*HH, 256, smem_bytes>>>((const float*)xh, omv, wBv, b_v, out);
}

// round 7
// speedup vs baseline: 1.3081x; 1.0525x over previous
#include <cuda_runtime.h>
#include <math.h>
#include <stdint.h>

#define BB 8
#define CH 64
#define HH 128
#define WW 128

typedef unsigned long long u64;

// ---------------- scratch (device globals; no allocation allowed) ----------
__device__ float g_x_nhwc[BB*HH*WW*CH];   // x transposed to NHWC
__device__ float g_xh_nhwc[BB*HH*WW*CH];  // horizontal-pass output, NHWC
__device__ float g_omh[BB*HH*WW*12];      // dy0,dx0,dy1,dx1,dy2,dx2,m0,m1,m2,pad
__device__ float g_omv[BB*HH*WW*12];
// Packed weight images: [pass][k][c][64 floats]; row = 32 u64 out-pairs:
// u64 pos = i2*16 + og*2 + t holds (w[2jg], w[2jg+1]), jg = og*4 + i2*2 + t
__device__ __align__(16) float g_wB[2][12288];

// ---------------- f32x2 packed helpers (Blackwell FFMA2) -------------------
static __device__ __forceinline__ u64 pk2(float a, float b) {
    u64 r; asm("mov.b64 %0, {%1,%2};" : "=l"(r) : "f"(a), "f"(b)); return r;
}
static __device__ __forceinline__ void upk2(u64 v, float &a, float &b) {
    asm("mov.b64 {%0,%1}, %2;" : "=f"(a), "=f"(b) : "l"(v));
}
static __device__ __forceinline__ u64 ffma2(u64 a, u64 b, u64 c) {
    u64 d; asm("fma.rn.f32x2 %0, %1, %2, %3;" : "=l"(d) : "l"(a), "l"(b), "l"(c)); return d;
}
static __device__ __forceinline__ u64 fmul2(u64 a, u64 b) {
    u64 d; asm("mul.rn.f32x2 %0, %1, %2;" : "=l"(d) : "l"(a), "l"(b)); return d;
}
static __device__ __forceinline__ float f4c(const float4 &v, int i) {
    return i == 0 ? v.x : (i == 1 ? v.y : (i == 2 ? v.z : v.w));
}

// ---------------- K-1: weight repack (runs once, tiny) ---------------------
__global__ __launch_bounds__(256) void prep_weights(
    const float* __restrict__ wh, const float* __restrict__ wv)
{
    int i = blockIdx.x*256 + threadIdx.x;
    if (i >= 24576) return;
    int pass = i / 12288;
    int r = i % 12288;
    int k = r / 4096;
    int rr = r % 4096;
    int c = rr / 64;
    int f = rr % 64;
    int pos = f >> 1, e = f & 1;
    int i2 = pos >> 4, og = (pos >> 1) & 7, t = pos & 1;
    int jg = og*4 + i2*2 + t;
    int o = 2*jg + e;
    const float* w = pass ? wv : wh;
    g_wB[pass][r] = w[o*192 + c*3 + k];
}

// ---------------- K0: NCHW -> NHWC transpose -------------------------------
__global__ __launch_bounds__(256) void transpose_kernel(const float* __restrict__ in) {
    __shared__ float tile[CH][33];
    int n = blockIdx.z, y = blockIdx.y, x0 = blockIdx.x * 32;
    int tx = threadIdx.x, ty = threadIdx.y;
    #pragma unroll
    for (int c = ty; c < CH; c += 8)
        tile[c][tx] = in[(((size_t)n*CH + c)*HH + y)*WW + x0 + tx];
    __syncthreads();
    int t = ty*32 + tx;
    #pragma unroll
    for (int i = 0; i < 8; i++) {
        int idx = t + i*256;
        int px = idx >> 6, c = idx & 63;
        g_x_nhwc[(((size_t)n*HH + y)*WW + x0 + px)*CH + c] = tile[c][px];
    }
}

// ---------------- K1: offsets + masks, 2 pixels (adjacent rows) / thread ---
__global__ __launch_bounds__(256, 2) void offmask_kernel(
    const float* __restrict__ woh, const float* __restrict__ boh,
    const float* __restrict__ wmh, const float* __restrict__ bmh,
    const float* __restrict__ wov, const float* __restrict__ bov,
    const float* __restrict__ wmv, const float* __restrict__ bmv)
{
    __shared__ float ws[64*6*12];
    int tid = threadIdx.x;
    for (int i = tid; i < 64*6*12; i += 256) {
        int o = i % 12, j = (i/12) % 6, c = i/72;
        float v = 0.f;
        if (o < 6)      v = (j < 3) ? woh[o*192 + c*3 + j] : wov[o*192 + c*3 + (j-3)];
        else if (o < 9) v = (j < 3) ? wmh[(o-6)*192 + c*3 + j] : wmv[(o-6)*192 + c*3 + (j-3)];
        ws[i] = v;
    }
    __syncthreads();

    int x = tid & 127;
    int pairidx = blockIdx.x*2 + (tid >> 7);   // 0..511
    int row0 = pairidx*2;
    int y = row0 & 127;
    size_t p0 = (size_t)row0*WW + x;
    size_t p1 = p0 + WW;

    u64 H0a=0,H0b=0,H0c=0,H0d=0, V0a=0,V0b=0,V0c=0,V0d=0;
    u64 H1a=0,H1b=0,H1c=0,H1d=0, V1a=0,V1b=0,V1c=0,V1d=0;
    float H0e=0.f, V0e=0.f, H1e=0.f, V1e=0.f;

    const float* pc0 = g_x_nhwc + p0*CH;
    const float* pc1 = g_x_nhwc + p1*CH;
    bool hl = x > 0, hr = x < WW-1;
    bool vu = y > 0, vd = (y + 2) < HH;
    const float* pl0 = pc0 - CH;
    const float* pr0 = pc0 + CH;
    const float* pl1 = pc1 - CH;
    const float* pr1 = pc1 + CH;
    const float* pu  = pc0 - (size_t)WW*CH;
    const float* pd  = pc1 + (size_t)WW*CH;
    const float4 Z = make_float4(0.f,0.f,0.f,0.f);

    for (int c4 = 0; c4 < 16; c4++) {
        float4 fc0 = *(const float4*)(pc0 + c4*4);
        float4 fc1 = *(const float4*)(pc1 + c4*4);
        float4 fl0 = hl ? *(const float4*)(pl0 + c4*4) : Z;
        float4 fr0 = hr ? *(const float4*)(pr0 + c4*4) : Z;
        float4 fl1 = hl ? *(const float4*)(pl1 + c4*4) : Z;
        float4 fr1 = hr ? *(const float4*)(pr1 + c4*4) : Z;
        float4 fu  = vu ? *(const float4*)(pu  + c4*4) : Z;
        float4 fd  = vd ? *(const float4*)(pd  + c4*4) : Z;
        #pragma unroll
        for (int cc = 0; cc < 4; cc++) {
            int c = c4*4 + cc;
            float h0[3] = { f4c(fl0,cc), f4c(fc0,cc), f4c(fr0,cc) };
            float h1[3] = { f4c(fl1,cc), f4c(fc1,cc), f4c(fr1,cc) };
            float v0[3] = { f4c(fu,cc),  f4c(fc0,cc), f4c(fc1,cc) };
            float v1[3] = { f4c(fc0,cc), f4c(fc1,cc), f4c(fd,cc)  };
            #pragma unroll
            for (int j = 0; j < 3; j++) {
                const float* wb = &ws[(c*6 + j)*12];
                ulonglong2 W0 = *(const ulonglong2*)(wb);
                ulonglong2 W1 = *(const ulonglong2*)(wb + 4);
                float w8 = wb[8];
                u64 s0 = pk2(h0[j], h0[j]);
                H0a = ffma2(s0, W0.x, H0a); H0b = ffma2(s0, W0.y, H0b);
                H0c = ffma2(s0, W1.x, H0c); H0d = ffma2(s0, W1.y, H0d);
                H0e = fmaf(h0[j], w8, H0e);
                u64 s1 = pk2(h1[j], h1[j]);
                H1a = ffma2(s1, W0.x, H1a); H1b = ffma2(s1, W0.y, H1b);
                H1c = ffma2(s1, W1.x, H1c); H1d = ffma2(s1, W1.y, H1d);
                H1e = fmaf(h1[j], w8, H1e);

                const float* ub = &ws[(c*6 + j + 3)*12];
                ulonglong2 U0 = *(const ulonglong2*)(ub);
                ulonglong2 U1 = *(const ulonglong2*)(ub + 4);
                float u8 = ub[8];
                u64 t0 = pk2(v0[j], v0[j]);
                V0a = ffma2(t0, U0.x, V0a); V0b = ffma2(t0, U0.y, V0b);
                V0c = ffma2(t0, U1.x, V0c); V0d = ffma2(t0, U1.y, V0d);
                V0e = fmaf(v0[j], u8, V0e);
                u64 t1 = pk2(v1[j], v1[j]);
                V1a = ffma2(t1, U0.x, V1a); V1b = ffma2(t1, U0.y, V1b);
                V1c = ffma2(t1, U1.x, V1c); V1d = ffma2(t1, U1.y, V1d);
                V1e = fmaf(v1[j], u8, V1e);
            }
        }
    }

    float b0 = __ldg(boh+0), b1 = __ldg(boh+1), b2 = __ldg(boh+2);
    float b3 = __ldg(boh+3), b4 = __ldg(boh+4), b5 = __ldg(boh+5);
    float c0 = __ldg(bov+0), c1 = __ldg(bov+1), c2 = __ldg(bov+2);
    float c3 = __ldg(bov+3), c4b = __ldg(bov+4), c5 = __ldg(bov+5);
    float mb0 = __ldg(bmh+0), mb1 = __ldg(bmh+1), mb2 = __ldg(bmh+2);
    float nb0 = __ldg(bmv+0), nb1 = __ldg(bmv+1), nb2 = __ldg(bmv+2);

    #pragma unroll
    for (int r = 0; r < 2; r++) {
        float A[9], V[9];
        if (r == 0) {
            upk2(H0a,A[0],A[1]); upk2(H0b,A[2],A[3]); upk2(H0c,A[4],A[5]);
            upk2(H0d,A[6],A[7]); A[8]=H0e;
            upk2(V0a,V[0],V[1]); upk2(V0b,V[2],V[3]); upk2(V0c,V[4],V[5]);
            upk2(V0d,V[6],V[7]); V[8]=V0e;
        } else {
            upk2(H1a,A[0],A[1]); upk2(H1b,A[2],A[3]); upk2(H1c,A[4],A[5]);
            upk2(H1d,A[6],A[7]); A[8]=H1e;
            upk2(V1a,V[0],V[1]); upk2(V1b,V[2],V[3]); upk2(V1c,V[4],V[5]);
            upk2(V1d,V[6],V[7]); V[8]=V1e;
        }
        size_t p = r ? p1 : p0;
        float mh0 = 1.f/(1.f + expf(-(A[6] + mb0)));
        float mh1 = 1.f/(1.f + expf(-(A[7] + mb1)));
        float mh2 = 1.f/(1.f + expf(-(A[8] + mb2)));
        float mv0 = 1.f/(1.f + expf(-(V[6] + nb0)));
        float mv1 = 1.f/(1.f + expf(-(V[7] + nb1)));
        float mv2 = 1.f/(1.f + expf(-(V[8] + nb2)));
        float* oh = g_omh + p*12;
        *(float4*)(oh+0) = make_float4(A[0]+b0, A[1]+b1, A[2]+b2, A[3]+b3);
        *(float4*)(oh+4) = make_float4(A[4]+b4, A[5]+b5, mh0, mh1);
        oh[8] = mh2;
        float* ov = g_omv + p*12;
        *(float4*)(ov+0) = make_float4(V[0]+c0, V[1]+c1, V[2]+c2, V[3]+c3);
        *(float4*)(ov+4) = make_float4(V[4]+c4b, V[5]+c5, mv0, mv1);
        ov[8] = mv2;
    }
}

// ---------------- K2/K3: deformable axial pass ------------------------------
// Block = 128 thr, 1 row = 128 px x 64 outs; thread tile 8 px x 8 outs.
// smem floats: Bs 4096 (single tap) | As 64*128 (XOR-swizzled) | cww 1536 | cb 1536
#define SMF_B   0
#define SMF_A   4096
#define SMF_CW  (4096 + 8192)
#define SMF_CB  (SMF_CW + 1536)
#define SMF_TOT (SMF_CB + 1536)     // 15360 floats = 61440 B -> 3 CTAs/SM

template<int VERT, int OUT_NCHW>
__global__ __launch_bounds__(128, 3) void pass_kernel(
    const float* __restrict__ src,   // NHWC input
    const float* __restrict__ om,    // stride-12 offset/mask records
    const float* __restrict__ wB,    // packed weights [3][64][64]
    const float* __restrict__ bias,
    float* __restrict__ dst)
{
    extern __shared__ float smem[];
    float* Bs   = smem + SMF_B;
    float* As   = smem + SMF_A;
    float* cww  = smem + SMF_CW;
    int*  cbase = (int*)(smem + SMF_CB);

    int tid = threadIdx.x, wid = tid >> 5, lane = tid & 31;
    int row = blockIdx.x;            // n*H + y
    int n = row >> 7, y = row & 127;

    // per-pixel, per-tap corner weights + clamped base offsets
    for (int t = tid; t < 384; t += 128) {
        int k = t >> 7, xp = t & 127;
        const float* omb = om + ((size_t)row*WW + xp)*12;
        float dyk = omb[2*k], dxk = omb[2*k + 1], mkk = omb[6 + k];
        float py = (float)y + dyk + (VERT ? (float)(k-1) : 0.f);
        float pxf = (float)xp + dxk + (VERT ? 0.f : (float)(k-1));
        float y0f = floorf(py), x0f = floorf(pxf);
        float wy = py - y0f, wx = pxf - x0f;
        int iy0 = (int)y0f, ix0 = (int)x0f;
        int iy1 = iy0 + 1,  ix1 = ix0 + 1;
        float vy0 = (iy0 >= 0 && iy0 < HH) ? 1.f : 0.f;
        float vy1 = (iy1 >= 0 && iy1 < HH) ? 1.f : 0.f;
        float vx0 = (ix0 >= 0 && ix0 < WW) ? 1.f : 0.f;
        float vx1 = (ix1 >= 0 && ix1 < WW) ? 1.f : 0.f;
        float* cw = &cww[(k*128 + xp)*4];
        cw[0] = (1.f-wy)*(1.f-wx)*vy0*vx0*mkk;
        cw[1] = (1.f-wy)*wx      *vy0*vx1*mkk;
        cw[2] = wy*(1.f-wx)      *vy1*vx0*mkk;
        cw[3] = wy*wx            *vy1*vx1*mkk;
        int cy0 = min(max(iy0,0),HH-1), cy1 = min(max(iy1,0),HH-1);
        int cx0 = min(max(ix0,0),WW-1), cx1 = min(max(ix1,0),WW-1);
        int* cb = &cbase[(k*128 + xp)*4];
        cb[0] = ((n*HH + cy0)*WW + cx0)*CH;
        cb[1] = ((n*HH + cy0)*WW + cx1)*CH;
        cb[2] = ((n*HH + cy1)*WW + cx0)*CH;
        cb[3] = ((n*HH + cy1)*WW + cx1)*CH;
    }
    __syncthreads();

    int p8 = lane >> 3, c8l = lane & 7;     // gather lane roles
    int og = tid & 7, pgr = tid >> 3;       // phase-B: outs og*8.., px pgr*8..

    u64 acc[8][4];
    #pragma unroll
    for (int i = 0; i < 8; i++)
        #pragma unroll
        for (int j = 0; j < 4; j++) acc[i][j] = 0ull;

    for (int k = 0; k < 3; k++) {
        if (k) __syncthreads();

        // -------- stage this tap's weights (coalesced, 16 KB) --------------
        {
            const float4* s4 = (const float4*)(wB + k*4096);
            float4* d4 = (float4*)Bs;
            #pragma unroll
            for (int i = 0; i < 8; i++)
                d4[tid + i*128] = s4[tid + i*128];
        }

        // -------- gather: bilinear samples -> As[c][px], XOR-swizzled ------
        #pragma unroll
        for (int i = 0; i < 8; i++) {
            int pxg = wid*8 + i;                 // pixel group (4 px)
            int px = pxg*4 + p8;
            const float* cw = &cww[(k*128 + px)*4];
            const int*   cb = &cbase[(k*128 + px)*4];
            u64 w00p = pk2(cw[0], cw[0]);
            u64 w01p = pk2(cw[1], cw[1]);
            u64 w10p = pk2(cw[2], cw[2]);
            u64 w11p = pk2(cw[3], cw[3]);
            int b00 = cb[0], b01 = cb[1], b10 = cb[2], b11 = cb[3];
            #pragma unroll
            for (int h = 0; h < 2; h++) {
                int c4g = h*8 + c8l;             // channel group 0..15
                int co = c4g*4;
                ulonglong2 q00 = *(const ulonglong2*)(src + b00 + co);
                ulonglong2 q01 = *(const ulonglong2*)(src + b01 + co);
                ulonglong2 q10 = *(const ulonglong2*)(src + b10 + co);
                ulonglong2 q11 = *(const ulonglong2*)(src + b11 + co);
                u64 r01 = ffma2(w00p, q00.x, ffma2(w01p, q01.x,
                          ffma2(w10p, q10.x, fmul2(w11p, q11.x))));
                u64 r23 = ffma2(w00p, q00.y, ffma2(w01p, q01.y,
                          ffma2(w10p, q10.y, fmul2(w11p, q11.y))));
                float r0, r1, r2, r3;
                upk2(r01, r0, r1); upk2(r23, r2, r3);
                int base = ((pxg ^ (c4g & 7)) << 2) + p8;
                float* ar = As + co*128 + base;
                ar[0*128] = r0;
                ar[1*128] = r1;
                ar[2*128] = r2;
                ar[3*128] = r3;
            }
        }
        __syncthreads();

        // -------- phase B: 64-channel GEMM accumulate ----------------------
        #pragma unroll 4
        for (int c = 0; c < 64; c++) {
            int s = (c >> 2) & 7;
            const float* arow = As + c*128;
            float4 a0 = *(const float4*)(arow + (((2*pgr)     ^ s) << 2));
            float4 a1 = *(const float4*)(arow + (((2*pgr + 1) ^ s) << 2));
            const float* brow = Bs + c*64;
            ulonglong2 bp0 = *(const ulonglong2*)(brow + og*4);       // outs 0-3
            ulonglong2 bp1 = *(const ulonglong2*)(brow + 32 + og*4);  // outs 4-7
            u64 W0 = bp0.x, W1 = bp0.y, W2 = bp1.x, W3 = bp1.y;
            #pragma unroll
            for (int i = 0; i < 8; i++) {
                float av = (i < 4) ? f4c(a0, i) : f4c(a1, i - 4);
                u64 ad = pk2(av, av);
                acc[i][0] = ffma2(ad, W0, acc[i][0]);
                acc[i][1] = ffma2(ad, W1, acc[i][1]);
                acc[i][2] = ffma2(ad, W2, acc[i][2]);
                acc[i][3] = ffma2(ad, W3, acc[i][3]);
            }
        }
    }

    // -------- epilogue: add bias, store -----------------------------------
    float bv[8];
    #pragma unroll
    for (int m = 0; m < 8; m++) bv[m] = __ldg(bias + og*8 + m);

    if (OUT_NCHW) {
        #pragma unroll
        for (int m = 0; m < 8; m++) {
            int j = m >> 1, t = m & 1;
            float v[8];
            #pragma unroll
            for (int i = 0; i < 8; i++) {
                float lo, hi; upk2(acc[i][j], lo, hi);
                v[i] = (t ? hi : lo) + bv[m];
            }
            float* db = dst + (((size_t)(n*CH + og*8 + m))*HH + y)*WW + pgr*8;
            *(float4*)(db)     = make_float4(v[0], v[1], v[2], v[3]);
            *(float4*)(db + 4) = make_float4(v[4], v[5], v[6], v[7]);
        }
    } else {
        #pragma unroll
        for (int i = 0; i < 8; i++) {
            int px = pgr*8 + i;
            float s[8];
            #pragma unroll
            for (int j = 0; j < 4; j++) {
                float lo, hi; upk2(acc[i][j], lo, hi);
                s[2*j]   = lo + bv[2*j];
                s[2*j+1] = hi + bv[2*j+1];
            }
            float* db = dst + ((size_t)row*WW + px)*CH + og*8;
            *(float4*)(db)     = make_float4(s[0], s[1], s[2], s[3]);
            *(float4*)(db + 4) = make_float4(s[4], s[5], s[6], s[7]);
        }
    }
}

// ---------------- launch ---------------------------------------------------
extern "C" void kernel_launch(void* const* d_in, const int* in_sizes, int n_in,
                              void* d_out, int out_size) {
    const float* x        = (const float*)d_in[0];
    const float* w_off_h  = (const float*)d_in[1];
    const float* b_off_h  = (const float*)d_in[2];
    const float* w_mask_h = (const float*)d_in[3];
    const float* b_mask_h = (const float*)d_in[4];
    const float* w_off_v  = (const float*)d_in[5];
    const float* b_off_v  = (const float*)d_in[6];
    const float* w_mask_v = (const float*)d_in[7];
    const float* b_mask_v = (const float*)d_in[8];
    const float* w_h      = (const float*)d_in[9];
    const float* b_h      = (const float*)d_in[10];
    const float* w_v      = (const float*)d_in[11];
    const float* b_v      = (const float*)d_in[12];
    float* out = (float*)d_out;

    void *xn_p, *xh_p, *omh_p, *omv_p, *wB_p;
    cudaGetSymbolAddress(&xn_p,  g_x_nhwc);
    cudaGetSymbolAddress(&xh_p,  g_xh_nhwc);
    cudaGetSymbolAddress(&omh_p, g_omh);
    cudaGetSymbolAddress(&omv_p, g_omv);
    cudaGetSymbolAddress(&wB_p,  g_wB);
    const float* xn  = (const float*)xn_p;
    float*       xh  = (float*)xh_p;
    const float* omh = (const float*)omh_p;
    const float* omv = (const float*)omv_p;
    const float* wBh = (const float*)wB_p;
    const float* wBv = wBh + 12288;

    int smem_bytes = SMF_TOT * 4;   // 61440 B
    cudaFuncSetAttribute(pass_kernel<0,0>,
                         cudaFuncAttributeMaxDynamicSharedMemorySize, smem_bytes);
    cudaFuncSetAttribute(pass_kernel<1,1>,
                         cudaFuncAttributeMaxDynamicSharedMemorySize, smem_bytes);

    prep_weights<<<96, 256>>>(w_h, w_v);

    transpose_kernel<<<dim3(WW/32, HH, BB), dim3(32, 8)>>>(x);

    offmask_kernel<<<BB*HH/4, 256>>>(w_off_h, b_off_h, w_mask_h, b_mask_h,
                                     w_off_v, b_off_v, w_mask_v, b_mask_v);

    pass_kernel<0, 0><<<BB*HH, 128, smem_bytes>>>(xn, omh, wBh, b_h, xh);
    pass_kernel<1, 1><<<BB*HH, 128, smem_bytes>>>((const float*)xh, omv, wBv, b_v, out);
}